// round 1
// baseline (speedup 1.0000x reference)
#include <cuda_runtime.h>
#include <math.h>

// Problem constants
#define BATCH 2
#define SEQ   1024
#define TKN   2048      // BATCH*SEQ
#define HIDN  2048
#define NHEADS 32
#define KVN   512       // G*HD = 8*64
#define HD    64

// Scratch (static device arrays: no allocation allowed)
__device__ float g_Q[TKN * HIDN];
__device__ float g_K[TKN * KVN];
__device__ float g_V[TKN * KVN];
__device__ float g_A[TKN * HIDN];

// ---------------------------------------------------------------------------
// fast exp2 via FFMA polynomial (avoids MUFU throughput floor, rt_SMSP=8)
// input x <= 0 (score - rowmax), in log2 domain
// ---------------------------------------------------------------------------
__device__ __forceinline__ float fast_exp2(float x) {
    x = fmaxf(x, -125.0f);
    int n = __float2int_rn(x);
    float f = x - (float)n;                       // f in [-0.5, 0.5]
    float p = 1.5403530393381609e-4f;             // ln2^6/720
    p = fmaf(p, f, 1.3333558146428443e-3f);       // ln2^5/120
    p = fmaf(p, f, 9.6181291076284772e-3f);       // ln2^4/24
    p = fmaf(p, f, 5.5504108664821580e-2f);       // ln2^3/6
    p = fmaf(p, f, 2.4022650695910071e-1f);       // ln2^2/2
    p = fmaf(p, f, 6.9314718055994531e-1f);       // ln2
    p = fmaf(p, f, 1.0f);
    return __int_as_float((n + 127) << 23) * p;
}

// ---------------------------------------------------------------------------
// SGEMM: C[M,N] = A[M,K] @ B[K,N] + bias (+ resid). 128x128x8 tile, 8x8 micro.
// blockIdx.z==1 switches to (B2,bias2,C2) so K/V projections share one launch.
// M,N multiples of 128; K multiple of 8.
// ---------------------------------------------------------------------------
__global__ __launch_bounds__(256) void gemm_kernel(
    const float* __restrict__ A,
    const float* __restrict__ B,  const float* __restrict__ bias,  float* __restrict__ C,
    const float* __restrict__ B2, const float* __restrict__ bias2, float* __restrict__ C2,
    const float* __restrict__ resid,
    int M, int N, int K)
{
    if (blockIdx.z == 1) { B = B2; bias = bias2; C = C2; }

    __shared__ float As[8][132];   // transposed A tile, padded (conflict-free)
    __shared__ float Bs[8][128];

    const int tid = threadIdx.x;
    const int tx = tid & 15, ty = tid >> 4;
    const int mb = blockIdx.y * 128, nb = blockIdx.x * 128;

    const int arow = tid >> 1, ac = (tid & 1) * 4;
    const int brow = tid >> 5, bc = (tid & 31) * 4;

    float acc[8][8];
    #pragma unroll
    for (int i = 0; i < 8; i++)
        #pragma unroll
        for (int j = 0; j < 8; j++) acc[i][j] = 0.0f;

    for (int k0 = 0; k0 < K; k0 += 8) {
        float4 av = *(const float4*)&A[(size_t)(mb + arow) * K + k0 + ac];
        float4 bv = *(const float4*)&B[(size_t)(k0 + brow) * N + nb + bc];
        __syncthreads();
        As[ac + 0][arow] = av.x;
        As[ac + 1][arow] = av.y;
        As[ac + 2][arow] = av.z;
        As[ac + 3][arow] = av.w;
        *(float4*)&Bs[brow][bc] = bv;
        __syncthreads();

        #pragma unroll
        for (int kk = 0; kk < 8; kk++) {
            float ra[8], rb[8];
            *(float4*)&ra[0] = *(const float4*)&As[kk][ty * 8];
            *(float4*)&ra[4] = *(const float4*)&As[kk][ty * 8 + 4];
            *(float4*)&rb[0] = *(const float4*)&Bs[kk][tx * 8];
            *(float4*)&rb[4] = *(const float4*)&Bs[kk][tx * 8 + 4];
            #pragma unroll
            for (int i = 0; i < 8; i++)
                #pragma unroll
                for (int j = 0; j < 8; j++)
                    acc[i][j] = fmaf(ra[i], rb[j], acc[i][j]);
        }
    }

    const int row0 = mb + ty * 8, col0 = nb + tx * 8;
    float bb[8];
    #pragma unroll
    for (int j = 0; j < 8; j++) bb[j] = bias[col0 + j];

    #pragma unroll
    for (int i = 0; i < 8; i++) {
        const int row = row0 + i;
        if (resid) {
            #pragma unroll
            for (int j = 0; j < 8; j++)
                C[(size_t)row * N + col0 + j] =
                    acc[i][j] + bb[j] + resid[(size_t)row * N + col0 + j];
        } else {
            #pragma unroll
            for (int j = 0; j < 8; j++)
                C[(size_t)row * N + col0 + j] = acc[i][j] + bb[j];
        }
    }
}

// ---------------------------------------------------------------------------
// Attention: one block = (batch b, head h, 32 query rows).
// scores for 32x1024 kept in smem (padded stride 1025); k-tile transposed
// [64][65]; v-tile natural [64][72] for float4 reads. scale & log2e folded
// into q. Multiplicative mask applied pre-softmax. exp2 polynomial softmax.
// ---------------------------------------------------------------------------
#define SC_STRIDE 1025
#define Q_OFF   0
#define SC_OFF  (32 * 65)                 // 2080
#define KV_OFF  (SC_OFF + 32 * SC_STRIDE) // 2080 + 32800 = 34880
#define RS_OFF  (KV_OFF + 64 * 72)        // 34880 + 4608 = 39488
#define ATT_SMEM_FLOATS (RS_OFF + 32)     // 39520 floats = 158080 B

__global__ __launch_bounds__(256) void attn_kernel(
    const float* __restrict__ Q, const float* __restrict__ K,
    const float* __restrict__ V, const float* __restrict__ mask,
    float* __restrict__ Aout)
{
    extern __shared__ float sm[];
    float* qs   = sm + Q_OFF;   // [32][65]
    float* sc   = sm + SC_OFF;  // [32][1025]
    float* kv   = sm + KV_OFF;  // kt [64][65] / vt [64][72]
    float* rsum = sm + RS_OFF;  // [32]

    const int tid = threadIdx.x;
    const int b = blockIdx.z, h = blockIdx.y, g = h >> 2;  // R = 4
    const int q0 = blockIdx.x * 32;
    const int tb = b * SEQ;

    const float qscale = 1.4426950408889634f / 8.0f;  // log2(e) / sqrt(HD)

    // load + prescale q tile [32][64]
    #pragma unroll
    for (int i = 0; i < 8; i++) {
        int idx = tid + 256 * i;
        int r = idx >> 6, d = idx & 63;
        qs[r * 65 + d] = Q[(size_t)(tb + q0 + r) * HIDN + h * 64 + d] * qscale;
    }
    __syncthreads();

    const int jl = tid & 15, rp = tid >> 4;

    // ---- QK^T (scores in log2 domain) ----
    for (int t = 0; t < 16; t++) {
        #pragma unroll
        for (int i = 0; i < 16; i++) {
            int idx = tid + 256 * i;
            int j = idx >> 6, d = idx & 63;
            kv[d * 65 + j] = K[(size_t)(tb + t * 64 + j) * KVN + g * 64 + d];
        }
        __syncthreads();

        float s0[4] = {0, 0, 0, 0}, s1[4] = {0, 0, 0, 0};
        #pragma unroll
        for (int d = 0; d < 64; d++) {
            float qa = qs[rp * 65 + d];
            float qb = qs[(rp + 16) * 65 + d];
            const float* kr = &kv[d * 65 + jl * 4];
            #pragma unroll
            for (int i = 0; i < 4; i++) {
                float kk = kr[i];
                s0[i] = fmaf(qa, kk, s0[i]);
                s1[i] = fmaf(qb, kk, s1[i]);
            }
        }
        const float* mrow0 = &mask[(size_t)b * SEQ * SEQ + (size_t)(q0 + rp) * SEQ];
        const float* mrow1 = mrow0 + (size_t)16 * SEQ;
        #pragma unroll
        for (int i = 0; i < 4; i++) {
            int kj = t * 64 + jl * 4 + i;
            sc[rp * SC_STRIDE + kj]        = s0[i] * mrow0[kj];
            sc[(rp + 16) * SC_STRIDE + kj] = s1[i] * mrow1[kj];
        }
        __syncthreads();
    }

    // ---- softmax (unnormalized weights; row sums saved) ----
    {
        const int wid = tid >> 5, lane = tid & 31;
        #pragma unroll
        for (int r4 = 0; r4 < 4; r4++) {
            int r = wid * 4 + r4;
            float* row = &sc[r * SC_STRIDE];
            float mx = -1e30f;
            for (int c = lane; c < 1024; c += 32) mx = fmaxf(mx, row[c]);
            #pragma unroll
            for (int o = 16; o; o >>= 1) mx = fmaxf(mx, __shfl_xor_sync(0xffffffffu, mx, o));
            float sum = 0.0f;
            for (int c = lane; c < 1024; c += 32) {
                float p = fast_exp2(row[c] - mx);
                row[c] = p;
                sum += p;
            }
            #pragma unroll
            for (int o = 16; o; o >>= 1) sum += __shfl_xor_sync(0xffffffffu, sum, o);
            if (lane == 0) rsum[r] = sum;
        }
    }

    // ---- P @ V ----
    const int dl = tid & 15;
    float o0[4] = {0, 0, 0, 0}, o1[4] = {0, 0, 0, 0};
    for (int t = 0; t < 16; t++) {
        __syncthreads();   // protect kv reuse; first iter also publishes sc/rsum
        #pragma unroll
        for (int i = 0; i < 16; i++) {
            int idx = tid + 256 * i;
            int j = idx >> 6, d = idx & 63;
            kv[j * 72 + d] = V[(size_t)(tb + t * 64 + j) * KVN + g * 64 + d];
        }
        __syncthreads();

        #pragma unroll
        for (int j = 0; j < 64; j++) {
            float wa = sc[rp * SC_STRIDE + t * 64 + j];
            float wb = sc[(rp + 16) * SC_STRIDE + t * 64 + j];
            float4 vv = *(const float4*)&kv[j * 72 + dl * 4];
            o0[0] = fmaf(wa, vv.x, o0[0]);
            o0[1] = fmaf(wa, vv.y, o0[1]);
            o0[2] = fmaf(wa, vv.z, o0[2]);
            o0[3] = fmaf(wa, vv.w, o0[3]);
            o1[0] = fmaf(wb, vv.x, o1[0]);
            o1[1] = fmaf(wb, vv.y, o1[1]);
            o1[2] = fmaf(wb, vv.z, o1[2]);
            o1[3] = fmaf(wb, vv.w, o1[3]);
        }
    }

    const float inva = 1.0f / rsum[rp];
    const float invb = 1.0f / rsum[rp + 16];
    float4 w0 = make_float4(o0[0] * inva, o0[1] * inva, o0[2] * inva, o0[3] * inva);
    float4 w1 = make_float4(o1[0] * invb, o1[1] * invb, o1[2] * invb, o1[3] * invb);
    *(float4*)&Aout[(size_t)(tb + q0 + rp) * HIDN + h * 64 + dl * 4] = w0;
    *(float4*)&Aout[(size_t)(tb + q0 + rp + 16) * HIDN + h * 64 + dl * 4] = w1;
}

// ---------------------------------------------------------------------------
// launch
// ---------------------------------------------------------------------------
extern "C" void kernel_launch(void* const* d_in, const int* in_sizes, int n_in,
                              void* d_out, int out_size)
{
    (void)in_sizes; (void)n_in; (void)out_size;
    const float* x    = (const float*)d_in[0];
    const float* mask = (const float*)d_in[1];
    const float* Wq   = (const float*)d_in[2];
    const float* bq   = (const float*)d_in[3];
    const float* Wk   = (const float*)d_in[4];
    const float* bk   = (const float*)d_in[5];
    const float* Wv   = (const float*)d_in[6];
    const float* bv   = (const float*)d_in[7];
    const float* Wo   = (const float*)d_in[8];
    const float* bo   = (const float*)d_in[9];
    float* out = (float*)d_out;

    float *Qp, *Kp, *Vp, *Ap;
    cudaGetSymbolAddress((void**)&Qp, g_Q);
    cudaGetSymbolAddress((void**)&Kp, g_K);
    cudaGetSymbolAddress((void**)&Vp, g_V);
    cudaGetSymbolAddress((void**)&Ap, g_A);

    const size_t attn_smem = ATT_SMEM_FLOATS * sizeof(float);
    cudaFuncSetAttribute(attn_kernel, cudaFuncAttributeMaxDynamicSharedMemorySize,
                         (int)attn_smem);

    // Q projection: [2048,2048] @ [2048,2048]
    gemm_kernel<<<dim3(16, 16, 1), 256>>>(x, Wq, bq, Qp,
                                          nullptr, nullptr, nullptr, nullptr,
                                          TKN, HIDN, HIDN);
    // K and V projections fused via gridDim.z: [2048,2048] @ [2048,512]
    gemm_kernel<<<dim3(4, 16, 2), 256>>>(x, Wk, bk, Kp,
                                         Wv, bv, Vp, nullptr,
                                         TKN, KVN, HIDN);
    // Attention
    attn_kernel<<<dim3(32, 32, 2), 256, attn_smem>>>(Qp, Kp, Vp, mask, Ap);
    // Output projection + bias + residual
    gemm_kernel<<<dim3(16, 16, 1), 256>>>(Ap, Wo, bo, out,
                                          nullptr, nullptr, nullptr, x,
                                          TKN, HIDN, HIDN);
}

// round 2
// speedup vs baseline: 3.3299x; 3.3299x over previous
#include <cuda_runtime.h>
#include <math.h>
#include <stdint.h>

// Problem constants
#define BATCH 2
#define SEQ   1024
#define TKN   2048      // BATCH*SEQ
#define HIDN  2048
#define NHEADS 32
#define KVN   512       // G*HD = 8*64
#define HD    64

// Scratch (static device arrays: no allocation allowed)
__device__ float g_Q[TKN * HIDN];
__device__ float g_K[TKN * KVN];
__device__ float g_V[TKN * KVN];
__device__ float g_A[TKN * HIDN];
__device__ float g_S[(size_t)BATCH * NHEADS * SEQ * SEQ];   // 256 MB scores

// ---------------------------------------------------------------------------
// helpers
// ---------------------------------------------------------------------------
__device__ __forceinline__ float tf32r(float x) {
    uint32_t u; asm("cvt.rna.tf32.f32 %0, %1;" : "=r"(u) : "f"(x));
    return __uint_as_float(u);
}
__device__ __forceinline__ float4 tf32r4(float4 v) {
    return make_float4(tf32r(v.x), tf32r(v.y), tf32r(v.z), tf32r(v.w));
}

// mma.sync m16n8k8 tf32: D = A*B + D (fp32 accum)
__device__ __forceinline__ void mma8(float d[4], const float a[4], const float b[2]) {
    const uint32_t* A = reinterpret_cast<const uint32_t*>(a);
    const uint32_t* B = reinterpret_cast<const uint32_t*>(b);
    asm volatile(
        "mma.sync.aligned.m16n8k8.row.col.f32.tf32.tf32.f32 "
        "{%0,%1,%2,%3}, {%4,%5,%6,%7}, {%8,%9}, {%0,%1,%2,%3};\n"
        : "+f"(d[0]), "+f"(d[1]), "+f"(d[2]), "+f"(d[3])
        : "r"(A[0]), "r"(A[1]), "r"(A[2]), "r"(A[3]), "r"(B[0]), "r"(B[1]));
}

// fast exp2 via FFMA polynomial (avoids MUFU throughput floor)
__device__ __forceinline__ float fast_exp2(float x) {
    x = fmaxf(x, -125.0f);
    int n = __float2int_rn(x);
    float f = x - (float)n;
    float p = 1.5403530393381609e-4f;
    p = fmaf(p, f, 1.3333558146428443e-3f);
    p = fmaf(p, f, 9.6181291076284772e-3f);
    p = fmaf(p, f, 5.5504108664821580e-2f);
    p = fmaf(p, f, 2.4022650695910071e-1f);
    p = fmaf(p, f, 6.9314718055994531e-1f);
    p = fmaf(p, f, 1.0f);
    return __int_as_float((n + 127) << 23) * p;
}

// ---------------------------------------------------------------------------
// tf32 GEMM: C[M,N] = A[M,K] @ B[K,N] + bias (+ resid).
// 128x128 block tile, 16-deep k-chunk, double-buffered smem.
// 8 warps in 2x4 grid; warp tile 64x32 = 4x4 mma tiles of m16n8k8.
// As[m][k] stride 20 (== 4 mod 32 -> frag bank = lane, conflict-free)
// Bs[k][n] stride 136 (== 8 mod 32 -> frag bank = 8k+n, conflict-free)
// blockIdx.z==1 switches to (B2,bias2,C2) so K/V projections fuse.
// ---------------------------------------------------------------------------
#define GA_STR 20
#define GB_STR 136

__global__ __launch_bounds__(256) void gemm_tf32_kernel(
    const float* __restrict__ A,
    const float* __restrict__ B,  const float* __restrict__ bias,  float* __restrict__ C,
    const float* __restrict__ B2, const float* __restrict__ bias2, float* __restrict__ C2,
    const float* __restrict__ resid,
    int M, int N, int K)
{
    if (blockIdx.z == 1) { B = B2; bias = bias2; C = C2; }

    __shared__ float As[2][128 * GA_STR];
    __shared__ float Bs[2][16 * GB_STR];

    const int tid = threadIdx.x, lane = tid & 31, warp = tid >> 5;
    const int wm = warp >> 2, wn = warp & 3;
    const int mb = blockIdx.y * 128, nb = blockIdx.x * 128;

    const int am = tid >> 2, ak = (tid & 3) * 4;   // A: 64 rows/pass, k 0..15
    const int bk = tid >> 5, bn = lane * 4;        // B: 8 k-rows/pass, n 0..127

    const float* Aptr = A + (size_t)(mb + am) * K + ak;
    const float* Bptr = B + (size_t)bk * N + nb + bn;

    float acc[4][4][4];
    #pragma unroll
    for (int i = 0; i < 4; i++)
        #pragma unroll
        for (int j = 0; j < 4; j++)
            #pragma unroll
            for (int q = 0; q < 4; q++) acc[i][j][q] = 0.0f;

    float4 ra0 = *(const float4*)(Aptr);
    float4 ra1 = *(const float4*)(Aptr + (size_t)64 * K);
    float4 rb0 = *(const float4*)(Bptr);
    float4 rb1 = *(const float4*)(Bptr + (size_t)8 * N);
    *(float4*)&As[0][am * GA_STR + ak]        = tf32r4(ra0);
    *(float4*)&As[0][(am + 64) * GA_STR + ak] = tf32r4(ra1);
    *(float4*)&Bs[0][bk * GB_STR + bn]        = tf32r4(rb0);
    *(float4*)&Bs[0][(bk + 8) * GB_STR + bn]  = tf32r4(rb1);
    __syncthreads();

    const int fm = wm * 64 + (lane >> 2);
    const int fn = wn * 32 + (lane >> 2);
    const int fk = lane & 3;

    const int nCh = K >> 4;
    for (int it = 0; it < nCh; it++) {
        const int cur = it & 1;
        if (it + 1 < nCh) {
            const float* ap = Aptr + (it + 1) * 16;
            const float* bp = Bptr + (size_t)(it + 1) * 16 * N;
            ra0 = *(const float4*)(ap);
            ra1 = *(const float4*)(ap + (size_t)64 * K);
            rb0 = *(const float4*)(bp);
            rb1 = *(const float4*)(bp + (size_t)8 * N);
        }
        #pragma unroll
        for (int kk = 0; kk < 2; kk++) {
            const int kb = kk * 8 + fk;
            float a[4][4], b[4][2];
            #pragma unroll
            for (int mt = 0; mt < 4; mt++) {
                const float* p = &As[cur][(fm + mt * 16) * GA_STR + kb];
                a[mt][0] = p[0];
                a[mt][1] = p[8 * GA_STR];
                a[mt][2] = p[4];
                a[mt][3] = p[8 * GA_STR + 4];
            }
            #pragma unroll
            for (int nt = 0; nt < 4; nt++) {
                const float* p = &Bs[cur][kb * GB_STR + fn + nt * 8];
                b[nt][0] = p[0];
                b[nt][1] = p[4 * GB_STR];
            }
            #pragma unroll
            for (int mt = 0; mt < 4; mt++)
                #pragma unroll
                for (int nt = 0; nt < 4; nt++)
                    mma8(acc[mt][nt], a[mt], b[nt]);
        }
        if (it + 1 < nCh) {
            const int nx = (it + 1) & 1;
            *(float4*)&As[nx][am * GA_STR + ak]        = tf32r4(ra0);
            *(float4*)&As[nx][(am + 64) * GA_STR + ak] = tf32r4(ra1);
            *(float4*)&Bs[nx][bk * GB_STR + bn]        = tf32r4(rb0);
            *(float4*)&Bs[nx][(bk + 8) * GB_STR + bn]  = tf32r4(rb1);
        }
        __syncthreads();
    }

    const int r0 = mb + wm * 64 + (lane >> 2);
    const int c0 = nb + wn * 32 + (lane & 3) * 2;
    #pragma unroll
    for (int mt = 0; mt < 4; mt++) {
        #pragma unroll
        for (int nt = 0; nt < 4; nt++) {
            const int r = r0 + mt * 16;
            const int c = c0 + nt * 8;
            const float bx = bias[c], by = bias[c + 1];
            float2 v0 = make_float2(acc[mt][nt][0] + bx, acc[mt][nt][1] + by);
            float2 v1 = make_float2(acc[mt][nt][2] + bx, acc[mt][nt][3] + by);
            if (resid) {
                const float2 u0 = *(const float2*)&resid[(size_t)r * N + c];
                const float2 u1 = *(const float2*)&resid[(size_t)(r + 8) * N + c];
                v0.x += u0.x; v0.y += u0.y; v1.x += u1.x; v1.y += u1.y;
            }
            *(float2*)&C[(size_t)r * N + c]       = v0;
            *(float2*)&C[(size_t)(r + 8) * N + c] = v1;
        }
    }
}

// ---------------------------------------------------------------------------
// QK^T batched NT gemm: scores[b,h] = (Q_h @ K_g^T) * (1/8) * mask[b]
// block = 128 q-rows x 128 k-cols, K=64 one-shot in smem.
// Qs[m][k], Ks[n][k], both stride 68 (==4 mod 32: frag bank = lane / 4n+k).
// ---------------------------------------------------------------------------
#define QK_STR 68
#define QK_SMEM (2 * 128 * QK_STR * 4)

__global__ __launch_bounds__(256) void qk_kernel(
    const float* __restrict__ Q, const float* __restrict__ K,
    const float* __restrict__ mask, float* __restrict__ S)
{
    extern __shared__ float sh[];
    float* Qs = sh;                 // [128][68]
    float* Ks = sh + 128 * QK_STR;  // [128][68]

    const int tid = threadIdx.x, lane = tid & 31, warp = tid >> 5;
    const int wm = warp >> 2, wn = warp & 3;
    const int z = blockIdx.z, b = z >> 5, h = z & 31, g = h >> 2;
    const int q0 = blockIdx.y * 128, n0 = blockIdx.x * 128;
    const size_t tb = (size_t)b * SEQ;

    const int lr = tid >> 4, lc = (tid & 15) * 4;
    #pragma unroll
    for (int p = 0; p < 8; p++) {
        const int m = lr + p * 16;
        float4 v = *(const float4*)&Q[(tb + q0 + m) * HIDN + h * 64 + lc];
        *(float4*)&Qs[m * QK_STR + lc] = tf32r4(v);
        float4 w = *(const float4*)&K[(tb + n0 + m) * KVN + g * 64 + lc];
        *(float4*)&Ks[m * QK_STR + lc] = tf32r4(w);
    }
    __syncthreads();

    float acc[4][4][4];
    #pragma unroll
    for (int i = 0; i < 4; i++)
        #pragma unroll
        for (int j = 0; j < 4; j++)
            #pragma unroll
            for (int q = 0; q < 4; q++) acc[i][j][q] = 0.0f;

    const int fm = wm * 64 + (lane >> 2);
    const int fn = wn * 32 + (lane >> 2);
    const int fk = lane & 3;

    #pragma unroll
    for (int ks = 0; ks < 8; ks++) {
        const int kb = ks * 8 + fk;
        float a[4][4], bf[4][2];
        #pragma unroll
        for (int mt = 0; mt < 4; mt++) {
            const float* p = &Qs[(fm + mt * 16) * QK_STR + kb];
            a[mt][0] = p[0];
            a[mt][1] = p[8 * QK_STR];
            a[mt][2] = p[4];
            a[mt][3] = p[8 * QK_STR + 4];
        }
        #pragma unroll
        for (int nt = 0; nt < 4; nt++) {
            const float* p = &Ks[(fn + nt * 8) * QK_STR + kb];
            bf[nt][0] = p[0];
            bf[nt][1] = p[4];
        }
        #pragma unroll
        for (int mt = 0; mt < 4; mt++)
            #pragma unroll
            for (int nt = 0; nt < 4; nt++)
                mma8(acc[mt][nt], a[mt], bf[nt]);
    }

    const int r0 = q0 + wm * 64 + (lane >> 2);
    const int c0 = n0 + wn * 32 + (lane & 3) * 2;
    const float sc = 0.125f;  // 1/sqrt(64)
    #pragma unroll
    for (int mt = 0; mt < 4; mt++) {
        #pragma unroll
        for (int nt = 0; nt < 4; nt++) {
            const int r = r0 + mt * 16;
            const int c = c0 + nt * 8;
            const size_t mrow = ((size_t)b * SEQ + r) * SEQ + c;
            const float2 m0 = *(const float2*)&mask[mrow];
            const float2 m1 = *(const float2*)&mask[mrow + (size_t)8 * SEQ];
            const size_t srow = ((size_t)z * SEQ + r) * SEQ + c;
            float2 o0 = make_float2(acc[mt][nt][0] * sc * m0.x, acc[mt][nt][1] * sc * m0.y);
            float2 o1 = make_float2(acc[mt][nt][2] * sc * m1.x, acc[mt][nt][3] * sc * m1.y);
            *(float2*)&S[srow]                  = o0;
            *(float2*)&S[srow + (size_t)8 * SEQ] = o1;
        }
    }
}

// ---------------------------------------------------------------------------
// Row softmax over g_S (in place, normalized). One warp per 1024-col row.
// ---------------------------------------------------------------------------
__global__ __launch_bounds__(256) void softmax_kernel(float* __restrict__ S)
{
    const int lane = threadIdx.x & 31, warp = threadIdx.x >> 5;
    const size_t row = (size_t)blockIdx.x * 8 + warp;
    float* p = S + row * SEQ;

    float4 v[8];
    float mx = -1e30f;
    #pragma unroll
    for (int i = 0; i < 8; i++) {
        v[i] = *(const float4*)&p[i * 128 + lane * 4];
        mx = fmaxf(mx, fmaxf(fmaxf(v[i].x, v[i].y), fmaxf(v[i].z, v[i].w)));
    }
    #pragma unroll
    for (int o = 16; o; o >>= 1) mx = fmaxf(mx, __shfl_xor_sync(0xffffffffu, mx, o));

    const float L2E = 1.4426950408889634f;
    float sum = 0.0f;
    #pragma unroll
    for (int i = 0; i < 8; i++) {
        v[i].x = fast_exp2((v[i].x - mx) * L2E);
        v[i].y = fast_exp2((v[i].y - mx) * L2E);
        v[i].z = fast_exp2((v[i].z - mx) * L2E);
        v[i].w = fast_exp2((v[i].w - mx) * L2E);
        sum += v[i].x + v[i].y + v[i].z + v[i].w;
    }
    #pragma unroll
    for (int o = 16; o; o >>= 1) sum += __shfl_xor_sync(0xffffffffu, sum, o);
    const float inv = 1.0f / sum;

    #pragma unroll
    for (int i = 0; i < 8; i++) {
        v[i].x *= inv; v[i].y *= inv; v[i].z *= inv; v[i].w *= inv;
        *(float4*)&p[i * 128 + lane * 4] = v[i];
    }
}

// ---------------------------------------------------------------------------
// PV batched NN gemm: out[b,h][1024,64] = P[1024,1024] @ V_g[1024,64]
// block = 128 rows x 64 cols, k-chunk 32, double-buffered.
// 8 warps 4x2; warp tile 32x32 = 2x4 mma tiles.
// Ps[m][k] stride 36, Vs[k][n] stride 68 (conflict-free frags).
// ---------------------------------------------------------------------------
#define PV_PSTR 36
#define PV_VSTR 68
#define PV_SMEM ((2 * 128 * PV_PSTR + 2 * 32 * PV_VSTR) * 4)

__global__ __launch_bounds__(256) void pv_kernel(
    const float* __restrict__ S, const float* __restrict__ V,
    float* __restrict__ Aout)
{
    extern __shared__ float sh[];
    float* Ps = sh;                      // [2][128*36]
    float* Vs = sh + 2 * 128 * PV_PSTR;  // [2][32*68]

    const int tid = threadIdx.x, lane = tid & 31, warp = tid >> 5;
    const int wm = warp >> 1, wn = warp & 1;
    const int z = blockIdx.y, b = z >> 5, h = z & 31, g = h >> 2;
    const int q0 = blockIdx.x * 128;
    const size_t tb = (size_t)b * SEQ;

    const int pm = tid >> 3, pk = (tid & 7) * 4;   // P: 32 rows/pass x 4
    const int vk = tid >> 4, vd = (tid & 15) * 4;  // V: 16 k-rows/pass x 2

    const float* Pbase = S + ((size_t)z * SEQ + q0) * SEQ;

    float acc[2][4][4];
    #pragma unroll
    for (int i = 0; i < 2; i++)
        #pragma unroll
        for (int j = 0; j < 4; j++)
            #pragma unroll
            for (int q = 0; q < 4; q++) acc[i][j][q] = 0.0f;

    float4 rp[4], rv[2];
    #pragma unroll
    for (int p4 = 0; p4 < 4; p4++)
        rp[p4] = *(const float4*)&Pbase[(size_t)(pm + p4 * 32) * SEQ + pk];
    #pragma unroll
    for (int p2 = 0; p2 < 2; p2++)
        rv[p2] = *(const float4*)&V[(tb + vk + p2 * 16) * KVN + g * 64 + vd];
    #pragma unroll
    for (int p4 = 0; p4 < 4; p4++)
        *(float4*)&Ps[(pm + p4 * 32) * PV_PSTR + pk] = tf32r4(rp[p4]);
    #pragma unroll
    for (int p2 = 0; p2 < 2; p2++)
        *(float4*)&Vs[(vk + p2 * 16) * PV_VSTR + vd] = tf32r4(rv[p2]);
    __syncthreads();

    const int fm = wm * 32 + (lane >> 2);
    const int fn = wn * 32 + (lane >> 2);
    const int fk = lane & 3;

    for (int it = 0; it < 32; it++) {
        const int cur = it & 1;
        if (it + 1 < 32) {
            const int kg = (it + 1) * 32;
            #pragma unroll
            for (int p4 = 0; p4 < 4; p4++)
                rp[p4] = *(const float4*)&Pbase[(size_t)(pm + p4 * 32) * SEQ + kg + pk];
            #pragma unroll
            for (int p2 = 0; p2 < 2; p2++)
                rv[p2] = *(const float4*)&V[(tb + kg + vk + p2 * 16) * KVN + g * 64 + vd];
        }
        #pragma unroll
        for (int kk = 0; kk < 4; kk++) {
            const int kb = kk * 8 + fk;
            float a[2][4], bf[4][2];
            #pragma unroll
            for (int mt = 0; mt < 2; mt++) {
                const float* p = &Ps[cur * 128 * PV_PSTR + (fm + mt * 16) * PV_PSTR + kb];
                a[mt][0] = p[0];
                a[mt][1] = p[8 * PV_PSTR];
                a[mt][2] = p[4];
                a[mt][3] = p[8 * PV_PSTR + 4];
            }
            #pragma unroll
            for (int nt = 0; nt < 4; nt++) {
                const float* p = &Vs[cur * 32 * PV_VSTR + kb * PV_VSTR + fn + nt * 8];
                bf[nt][0] = p[0];
                bf[nt][1] = p[4 * PV_VSTR];
            }
            #pragma unroll
            for (int mt = 0; mt < 2; mt++)
                #pragma unroll
                for (int nt = 0; nt < 4; nt++)
                    mma8(acc[mt][nt], a[mt], bf[nt]);
        }
        if (it + 1 < 32) {
            const int nx = (it + 1) & 1;
            #pragma unroll
            for (int p4 = 0; p4 < 4; p4++)
                *(float4*)&Ps[nx * 128 * PV_PSTR + (pm + p4 * 32) * PV_PSTR + pk] = tf32r4(rp[p4]);
            #pragma unroll
            for (int p2 = 0; p2 < 2; p2++)
                *(float4*)&Vs[nx * 32 * PV_VSTR + (vk + p2 * 16) * PV_VSTR + vd] = tf32r4(rv[p2]);
        }
        __syncthreads();
    }

    const int r0 = q0 + wm * 32 + (lane >> 2);
    const int c0 = wn * 32 + (lane & 3) * 2;
    #pragma unroll
    for (int mt = 0; mt < 2; mt++) {
        #pragma unroll
        for (int nt = 0; nt < 4; nt++) {
            const int r = r0 + mt * 16;
            const int c = c0 + nt * 8;
            *(float2*)&Aout[(tb + r) * HIDN + h * 64 + c] =
                make_float2(acc[mt][nt][0], acc[mt][nt][1]);
            *(float2*)&Aout[(tb + r + 8) * HIDN + h * 64 + c] =
                make_float2(acc[mt][nt][2], acc[mt][nt][3]);
        }
    }
}

// ---------------------------------------------------------------------------
// launch
// ---------------------------------------------------------------------------
extern "C" void kernel_launch(void* const* d_in, const int* in_sizes, int n_in,
                              void* d_out, int out_size)
{
    (void)in_sizes; (void)n_in; (void)out_size;
    const float* x    = (const float*)d_in[0];
    const float* mask = (const float*)d_in[1];
    const float* Wq   = (const float*)d_in[2];
    const float* bq   = (const float*)d_in[3];
    const float* Wk   = (const float*)d_in[4];
    const float* bk   = (const float*)d_in[5];
    const float* Wv   = (const float*)d_in[6];
    const float* bv   = (const float*)d_in[7];
    const float* Wo   = (const float*)d_in[8];
    const float* bo   = (const float*)d_in[9];
    float* out = (float*)d_out;

    float *Qp, *Kp, *Vp, *Ap, *Sp;
    cudaGetSymbolAddress((void**)&Qp, g_Q);
    cudaGetSymbolAddress((void**)&Kp, g_K);
    cudaGetSymbolAddress((void**)&Vp, g_V);
    cudaGetSymbolAddress((void**)&Ap, g_A);
    cudaGetSymbolAddress((void**)&Sp, g_S);

    cudaFuncSetAttribute(qk_kernel, cudaFuncAttributeMaxDynamicSharedMemorySize, QK_SMEM);
    cudaFuncSetAttribute(pv_kernel, cudaFuncAttributeMaxDynamicSharedMemorySize, PV_SMEM);

    // Q projection
    gemm_tf32_kernel<<<dim3(16, 16, 1), 256>>>(x, Wq, bq, Qp,
                                               nullptr, nullptr, nullptr, nullptr,
                                               TKN, HIDN, HIDN);
    // K and V projections fused via gridDim.z
    gemm_tf32_kernel<<<dim3(4, 16, 2), 256>>>(x, Wk, bk, Kp,
                                              Wv, bv, Vp, nullptr,
                                              TKN, KVN, HIDN);
    // scores = (Q K^T)/8 * mask
    qk_kernel<<<dim3(8, 8, 64), 256, QK_SMEM>>>(Qp, Kp, mask, Sp);
    // softmax rows
    softmax_kernel<<<dim3(8192), 256>>>(Sp);
    // out = P @ V
    pv_kernel<<<dim3(8, 64), 256, PV_SMEM>>>(Sp, Vp, Ap);
    // output projection + bias + residual
    gemm_tf32_kernel<<<dim3(16, 16, 1), 256>>>(Ap, Wo, bo, out,
                                               nullptr, nullptr, nullptr, x,
                                               TKN, HIDN, HIDN);
}

// round 3
// speedup vs baseline: 3.8728x; 1.1630x over previous
#include <cuda_runtime.h>
#include <math.h>
#include <stdint.h>

// Problem constants
#define BATCH 2
#define SEQ   1024
#define TKN   2048      // BATCH*SEQ
#define HIDN  2048
#define NHEADS 32
#define KVN   512       // G*HD = 8*64
#define HD    64

// Scratch (static device arrays: no allocation allowed)
__device__ float g_Q[TKN * HIDN];
__device__ float g_K[TKN * KVN];
__device__ float g_V[TKN * KVN];
__device__ float g_A[TKN * HIDN];

// ---------------------------------------------------------------------------
// helpers
// ---------------------------------------------------------------------------
__device__ __forceinline__ float tf32r(float x) {
    uint32_t u; asm("cvt.rna.tf32.f32 %0, %1;" : "=r"(u) : "f"(x));
    return __uint_as_float(u);
}
__device__ __forceinline__ float4 tf32r4(float4 v) {
    return make_float4(tf32r(v.x), tf32r(v.y), tf32r(v.z), tf32r(v.w));
}

// mma.sync m16n8k8 tf32: D = A*B + D (fp32 accum)
__device__ __forceinline__ void mma8(float d[4], const float a[4], const float b[2]) {
    const uint32_t* A = reinterpret_cast<const uint32_t*>(a);
    const uint32_t* B = reinterpret_cast<const uint32_t*>(b);
    asm volatile(
        "mma.sync.aligned.m16n8k8.row.col.f32.tf32.tf32.f32 "
        "{%0,%1,%2,%3}, {%4,%5,%6,%7}, {%8,%9}, {%0,%1,%2,%3};\n"
        : "+f"(d[0]), "+f"(d[1]), "+f"(d[2]), "+f"(d[3])
        : "r"(A[0]), "r"(A[1]), "r"(A[2]), "r"(A[3]), "r"(B[0]), "r"(B[1]));
}

// fast exp2 via FFMA polynomial (avoids MUFU throughput floor)
__device__ __forceinline__ float fast_exp2(float x) {
    x = fmaxf(x, -125.0f);
    int n = __float2int_rn(x);
    float f = x - (float)n;
    float p = 1.5403530393381609e-4f;
    p = fmaf(p, f, 1.3333558146428443e-3f);
    p = fmaf(p, f, 9.6181291076284772e-3f);
    p = fmaf(p, f, 5.5504108664821580e-2f);
    p = fmaf(p, f, 2.4022650695910071e-1f);
    p = fmaf(p, f, 6.9314718055994531e-1f);
    p = fmaf(p, f, 1.0f);
    return __int_as_float((n + 127) << 23) * p;
}

// ---------------------------------------------------------------------------
// tf32 GEMM core (128x128x16 double-buffered, 8 warps 2x4, warp 64x32).
// As[m][k] stride 20, Bs[k][n] stride 136 -> conflict-free fragment LDS.
// ---------------------------------------------------------------------------
#define GA_STR 20
#define GB_STR 136

// Fused Q/K/V projection: one launch, flattened tile grid.
// blockIdx.x in [0,16): Q cols; [16,20): K cols; [20,24): V cols.
__global__ __launch_bounds__(256) void qkv_gemm_kernel(
    const float* __restrict__ A,
    const float* __restrict__ Wq, const float* __restrict__ bq, float* __restrict__ Cq,
    const float* __restrict__ Wk, const float* __restrict__ bk, float* __restrict__ Ck,
    const float* __restrict__ Wv, const float* __restrict__ bv, float* __restrict__ Cv,
    int M, int K)
{
    const float* B; const float* bias; float* C; int N, nb;
    const int bx = blockIdx.x;
    if (bx < 16)      { B = Wq; bias = bq; C = Cq; N = HIDN; nb = bx * 128; }
    else if (bx < 20) { B = Wk; bias = bk; C = Ck; N = KVN;  nb = (bx - 16) * 128; }
    else              { B = Wv; bias = bv; C = Cv; N = KVN;  nb = (bx - 20) * 128; }

    __shared__ float As[2][128 * GA_STR];
    __shared__ float Bs[2][16 * GB_STR];

    const int tid = threadIdx.x, lane = tid & 31, warp = tid >> 5;
    const int wm = warp >> 2, wn = warp & 3;
    const int mb = blockIdx.y * 128;

    const int am = tid >> 2, ak = (tid & 3) * 4;
    const int bk_ = tid >> 5, bn = lane * 4;

    const float* Aptr = A + (size_t)(mb + am) * K + ak;
    const float* Bptr = B + (size_t)bk_ * N + nb + bn;

    float acc[4][4][4];
    #pragma unroll
    for (int i = 0; i < 4; i++)
        #pragma unroll
        for (int j = 0; j < 4; j++)
            #pragma unroll
            for (int q = 0; q < 4; q++) acc[i][j][q] = 0.0f;

    float4 ra0 = *(const float4*)(Aptr);
    float4 ra1 = *(const float4*)(Aptr + (size_t)64 * K);
    float4 rb0 = *(const float4*)(Bptr);
    float4 rb1 = *(const float4*)(Bptr + (size_t)8 * N);
    *(float4*)&As[0][am * GA_STR + ak]        = tf32r4(ra0);
    *(float4*)&As[0][(am + 64) * GA_STR + ak] = tf32r4(ra1);
    *(float4*)&Bs[0][bk_ * GB_STR + bn]       = tf32r4(rb0);
    *(float4*)&Bs[0][(bk_ + 8) * GB_STR + bn] = tf32r4(rb1);
    __syncthreads();

    const int fm = wm * 64 + (lane >> 2);
    const int fn = wn * 32 + (lane >> 2);
    const int fk = lane & 3;

    const int nCh = K >> 4;
    for (int it = 0; it < nCh; it++) {
        const int cur = it & 1;
        if (it + 1 < nCh) {
            const float* ap = Aptr + (it + 1) * 16;
            const float* bp = Bptr + (size_t)(it + 1) * 16 * N;
            ra0 = *(const float4*)(ap);
            ra1 = *(const float4*)(ap + (size_t)64 * K);
            rb0 = *(const float4*)(bp);
            rb1 = *(const float4*)(bp + (size_t)8 * N);
        }
        #pragma unroll
        for (int kk = 0; kk < 2; kk++) {
            const int kb = kk * 8 + fk;
            float a[4][4], b[4][2];
            #pragma unroll
            for (int mt = 0; mt < 4; mt++) {
                const float* p = &As[cur][(fm + mt * 16) * GA_STR + kb];
                a[mt][0] = p[0];
                a[mt][1] = p[8 * GA_STR];
                a[mt][2] = p[4];
                a[mt][3] = p[8 * GA_STR + 4];
            }
            #pragma unroll
            for (int nt = 0; nt < 4; nt++) {
                const float* p = &Bs[cur][kb * GB_STR + fn + nt * 8];
                b[nt][0] = p[0];
                b[nt][1] = p[4 * GB_STR];
            }
            #pragma unroll
            for (int mt = 0; mt < 4; mt++)
                #pragma unroll
                for (int nt = 0; nt < 4; nt++)
                    mma8(acc[mt][nt], a[mt], b[nt]);
        }
        if (it + 1 < nCh) {
            const int nx = (it + 1) & 1;
            *(float4*)&As[nx][am * GA_STR + ak]        = tf32r4(ra0);
            *(float4*)&As[nx][(am + 64) * GA_STR + ak] = tf32r4(ra1);
            *(float4*)&Bs[nx][bk_ * GB_STR + bn]       = tf32r4(rb0);
            *(float4*)&Bs[nx][(bk_ + 8) * GB_STR + bn] = tf32r4(rb1);
        }
        __syncthreads();
    }

    const int r0 = mb + wm * 64 + (lane >> 2);
    const int c0 = nb + wn * 32 + (lane & 3) * 2;
    #pragma unroll
    for (int mt = 0; mt < 4; mt++) {
        #pragma unroll
        for (int nt = 0; nt < 4; nt++) {
            const int r = r0 + mt * 16;
            const int c = c0 + nt * 8;
            const float bx_ = bias[c], by = bias[c + 1];
            *(float2*)&C[(size_t)r * N + c] =
                make_float2(acc[mt][nt][0] + bx_, acc[mt][nt][1] + by);
            *(float2*)&C[(size_t)(r + 8) * N + c] =
                make_float2(acc[mt][nt][2] + bx_, acc[mt][nt][3] + by);
        }
    }
}

// O projection with bias + residual.
__global__ __launch_bounds__(256) void gemm_tf32_kernel(
    const float* __restrict__ A,
    const float* __restrict__ B,  const float* __restrict__ bias,  float* __restrict__ C,
    const float* __restrict__ resid,
    int M, int N, int K)
{
    __shared__ float As[2][128 * GA_STR];
    __shared__ float Bs[2][16 * GB_STR];

    const int tid = threadIdx.x, lane = tid & 31, warp = tid >> 5;
    const int wm = warp >> 2, wn = warp & 3;
    const int mb = blockIdx.y * 128, nb = blockIdx.x * 128;

    const int am = tid >> 2, ak = (tid & 3) * 4;
    const int bk_ = tid >> 5, bn = lane * 4;

    const float* Aptr = A + (size_t)(mb + am) * K + ak;
    const float* Bptr = B + (size_t)bk_ * N + nb + bn;

    float acc[4][4][4];
    #pragma unroll
    for (int i = 0; i < 4; i++)
        #pragma unroll
        for (int j = 0; j < 4; j++)
            #pragma unroll
            for (int q = 0; q < 4; q++) acc[i][j][q] = 0.0f;

    float4 ra0 = *(const float4*)(Aptr);
    float4 ra1 = *(const float4*)(Aptr + (size_t)64 * K);
    float4 rb0 = *(const float4*)(Bptr);
    float4 rb1 = *(const float4*)(Bptr + (size_t)8 * N);
    *(float4*)&As[0][am * GA_STR + ak]        = tf32r4(ra0);
    *(float4*)&As[0][(am + 64) * GA_STR + ak] = tf32r4(ra1);
    *(float4*)&Bs[0][bk_ * GB_STR + bn]       = tf32r4(rb0);
    *(float4*)&Bs[0][(bk_ + 8) * GB_STR + bn] = tf32r4(rb1);
    __syncthreads();

    const int fm = wm * 64 + (lane >> 2);
    const int fn = wn * 32 + (lane >> 2);
    const int fk = lane & 3;

    const int nCh = K >> 4;
    for (int it = 0; it < nCh; it++) {
        const int cur = it & 1;
        if (it + 1 < nCh) {
            const float* ap = Aptr + (it + 1) * 16;
            const float* bp = Bptr + (size_t)(it + 1) * 16 * N;
            ra0 = *(const float4*)(ap);
            ra1 = *(const float4*)(ap + (size_t)64 * K);
            rb0 = *(const float4*)(bp);
            rb1 = *(const float4*)(bp + (size_t)8 * N);
        }
        #pragma unroll
        for (int kk = 0; kk < 2; kk++) {
            const int kb = kk * 8 + fk;
            float a[4][4], b[4][2];
            #pragma unroll
            for (int mt = 0; mt < 4; mt++) {
                const float* p = &As[cur][(fm + mt * 16) * GA_STR + kb];
                a[mt][0] = p[0];
                a[mt][1] = p[8 * GA_STR];
                a[mt][2] = p[4];
                a[mt][3] = p[8 * GA_STR + 4];
            }
            #pragma unroll
            for (int nt = 0; nt < 4; nt++) {
                const float* p = &Bs[cur][kb * GB_STR + fn + nt * 8];
                b[nt][0] = p[0];
                b[nt][1] = p[4 * GB_STR];
            }
            #pragma unroll
            for (int mt = 0; mt < 4; mt++)
                #pragma unroll
                for (int nt = 0; nt < 4; nt++)
                    mma8(acc[mt][nt], a[mt], b[nt]);
        }
        if (it + 1 < nCh) {
            const int nx = (it + 1) & 1;
            *(float4*)&As[nx][am * GA_STR + ak]        = tf32r4(ra0);
            *(float4*)&As[nx][(am + 64) * GA_STR + ak] = tf32r4(ra1);
            *(float4*)&Bs[nx][bk_ * GB_STR + bn]       = tf32r4(rb0);
            *(float4*)&Bs[nx][(bk_ + 8) * GB_STR + bn] = tf32r4(rb1);
        }
        __syncthreads();
    }

    const int r0 = mb + wm * 64 + (lane >> 2);
    const int c0 = nb + wn * 32 + (lane & 3) * 2;
    #pragma unroll
    for (int mt = 0; mt < 4; mt++) {
        #pragma unroll
        for (int nt = 0; nt < 4; nt++) {
            const int r = r0 + mt * 16;
            const int c = c0 + nt * 8;
            const float bx = bias[c], by = bias[c + 1];
            const float2 u0 = *(const float2*)&resid[(size_t)r * N + c];
            const float2 u1 = *(const float2*)&resid[(size_t)(r + 8) * N + c];
            *(float2*)&C[(size_t)r * N + c] =
                make_float2(acc[mt][nt][0] + bx + u0.x, acc[mt][nt][1] + by + u0.y);
            *(float2*)&C[(size_t)(r + 8) * N + c] =
                make_float2(acc[mt][nt][2] + bx + u1.x, acc[mt][nt][3] + by + u1.y);
        }
    }
}

// ---------------------------------------------------------------------------
// Fused flash attention: block = (b, h, 128 q rows), 8 k-tiles of 128 keys.
// No HBM score traffic. S-phase: warps 2x4, warp 64x32. PV: warp = 16 rows.
// P staged via smem (stride 132 -> conflict-free A-frags). Online softmax.
// ---------------------------------------------------------------------------
#define FA_QS   0
#define FA_KS   (128 * 68)
#define FA_VS   (2 * 128 * 68)
#define FA_PS   (3 * 128 * 68)
#define FA_RED  (FA_PS + 128 * 132)
#define FA_SUM  (FA_RED + 512)
#define FA_RM   (FA_SUM + 512)
#define FA_RL   (FA_RM + 128)
#define FA_AB   (FA_RL + 128)
#define FA_FLOATS (FA_AB + 128)
#define FA_SMEM   (FA_FLOATS * 4)

__global__ __launch_bounds__(256) void fa_kernel(
    const float* __restrict__ Q, const float* __restrict__ K,
    const float* __restrict__ V, const float* __restrict__ mask,
    float* __restrict__ Aout)
{
    extern __shared__ float sh[];
    float* Qs = sh + FA_QS;       // [128][68] (prescaled, tf32)
    float* Ks = sh + FA_KS;       // [128][68]
    float* Vs = sh + FA_VS;       // [128][68]
    float* Ps = sh + FA_PS;       // [128][132]
    float* red = sh + FA_RED;     // [4][128]
    float* sb  = sh + FA_SUM;     // [4][128]
    float* rm  = sh + FA_RM;      // [128] running max (log2 domain)
    float* rl  = sh + FA_RL;      // [128] running sum
    float* ab  = sh + FA_AB;      // [128] rescale alpha

    const int tid = threadIdx.x, lane = tid & 31, warp = tid >> 5;
    const int z = blockIdx.y, b = z >> 5, h = z & 31, g = h >> 2;
    const int q0 = blockIdx.x * 128;
    const size_t tb = (size_t)b * SEQ;
    const float* mbase = mask + (size_t)b * SEQ * SEQ;

    const int wm = warp >> 2, wn = warp & 3;
    const int fr = lane >> 2, fc = lane & 3;

    // load Q tile, prescale by (1/8)*log2(e)
    const float qsc = 0.125f * 1.4426950408889634f;
    {
        const int r = tid >> 4, c = (tid & 15) * 4;
        #pragma unroll
        for (int p = 0; p < 8; p++) {
            const int row = r + p * 16;
            float4 v = *(const float4*)&Q[(tb + q0 + row) * HIDN + h * 64 + c];
            v.x *= qsc; v.y *= qsc; v.z *= qsc; v.w *= qsc;
            *(float4*)&Qs[row * 68 + c] = tf32r4(v);
        }
    }
    if (tid < 128) { rm[tid] = -1e30f; rl[tid] = 0.0f; }

    float acc_o[8][4];
    #pragma unroll
    for (int i = 0; i < 8; i++)
        #pragma unroll
        for (int q = 0; q < 4; q++) acc_o[i][q] = 0.0f;

    for (int t = 0; t < 8; t++) {
        __syncthreads();  // prev PV done with Ks/Vs; first iter: Qs/rm ready
        // load K,V tiles
        {
            const int r = tid >> 4, c = (tid & 15) * 4;
            #pragma unroll
            for (int p = 0; p < 8; p++) {
                const int row = r + p * 16;
                const size_t goff = (tb + t * 128 + row) * KVN + g * 64 + c;
                *(float4*)&Ks[row * 68 + c] = tf32r4(*(const float4*)&K[goff]);
                *(float4*)&Vs[row * 68 + c] = tf32r4(*(const float4*)&V[goff]);
            }
        }
        __syncthreads();

        // ---- S = Qs @ Ks^T (warp 64x32) ----
        float s[4][4][4];
        #pragma unroll
        for (int i = 0; i < 4; i++)
            #pragma unroll
            for (int j = 0; j < 4; j++)
                #pragma unroll
                for (int q = 0; q < 4; q++) s[i][j][q] = 0.0f;

        #pragma unroll
        for (int ks = 0; ks < 8; ks++) {
            const int kb = ks * 8 + fc;
            float a[4][4], bf[4][2];
            #pragma unroll
            for (int mt = 0; mt < 4; mt++) {
                const float* p = &Qs[(wm * 64 + fr + mt * 16) * 68 + kb];
                a[mt][0] = p[0];
                a[mt][1] = p[8 * 68];
                a[mt][2] = p[4];
                a[mt][3] = p[8 * 68 + 4];
            }
            #pragma unroll
            for (int nt = 0; nt < 4; nt++) {
                const float* p = &Ks[(wn * 32 + fr + nt * 8) * 68 + kb];
                bf[nt][0] = p[0];
                bf[nt][1] = p[4];
            }
            #pragma unroll
            for (int mt = 0; mt < 4; mt++)
                #pragma unroll
                for (int nt = 0; nt < 4; nt++)
                    mma8(s[mt][nt], a[mt], bf[nt]);
        }

        // ---- mask multiply + per-row tile max ----
        #pragma unroll
        for (int mt = 0; mt < 4; mt++) {
            const int r0 = wm * 64 + mt * 16 + fr;
            float m0 = -1e30f, m1 = -1e30f;
            #pragma unroll
            for (int nt = 0; nt < 4; nt++) {
                const int cg = t * 128 + wn * 32 + nt * 8 + 2 * fc;
                const float2 k0 = *(const float2*)&mbase[(size_t)(q0 + r0) * SEQ + cg];
                const float2 k1 = *(const float2*)&mbase[(size_t)(q0 + r0 + 8) * SEQ + cg];
                s[mt][nt][0] *= k0.x; s[mt][nt][1] *= k0.y;
                s[mt][nt][2] *= k1.x; s[mt][nt][3] *= k1.y;
                m0 = fmaxf(m0, fmaxf(s[mt][nt][0], s[mt][nt][1]));
                m1 = fmaxf(m1, fmaxf(s[mt][nt][2], s[mt][nt][3]));
            }
            m0 = fmaxf(m0, __shfl_xor_sync(0xffffffffu, m0, 1));
            m0 = fmaxf(m0, __shfl_xor_sync(0xffffffffu, m0, 2));
            m1 = fmaxf(m1, __shfl_xor_sync(0xffffffffu, m1, 1));
            m1 = fmaxf(m1, __shfl_xor_sync(0xffffffffu, m1, 2));
            if (fc == 0) {
                red[wn * 128 + r0]     = m0;
                red[wn * 128 + r0 + 8] = m1;
            }
        }
        __syncthreads();

        // ---- p = exp2(s - m_new), stage P, partial sums ----
        #pragma unroll
        for (int mt = 0; mt < 4; mt++) {
            const int r0 = wm * 64 + mt * 16 + fr;
            const int r1 = r0 + 8;
            float mn0 = fmaxf(fmaxf(red[r0], red[128 + r0]),
                              fmaxf(red[256 + r0], red[384 + r0]));
            float mn1 = fmaxf(fmaxf(red[r1], red[128 + r1]),
                              fmaxf(red[256 + r1], red[384 + r1]));
            mn0 = fmaxf(mn0, rm[r0]);
            mn1 = fmaxf(mn1, rm[r1]);
            float s0 = 0.0f, s1 = 0.0f;
            #pragma unroll
            for (int nt = 0; nt < 4; nt++) {
                const float p0 = fast_exp2(s[mt][nt][0] - mn0);
                const float p1 = fast_exp2(s[mt][nt][1] - mn0);
                const float p2 = fast_exp2(s[mt][nt][2] - mn1);
                const float p3 = fast_exp2(s[mt][nt][3] - mn1);
                s0 += p0 + p1; s1 += p2 + p3;
                const int c = wn * 32 + nt * 8 + 2 * fc;
                *(float2*)&Ps[r0 * 132 + c] = make_float2(tf32r(p0), tf32r(p1));
                *(float2*)&Ps[r1 * 132 + c] = make_float2(tf32r(p2), tf32r(p3));
            }
            s0 += __shfl_xor_sync(0xffffffffu, s0, 1);
            s0 += __shfl_xor_sync(0xffffffffu, s0, 2);
            s1 += __shfl_xor_sync(0xffffffffu, s1, 1);
            s1 += __shfl_xor_sync(0xffffffffu, s1, 2);
            if (fc == 0) {
                sb[wn * 128 + r0] = s0;
                sb[wn * 128 + r1] = s1;
            }
        }
        __syncthreads();

        // ---- per-row running state update ----
        if (tid < 128) {
            const float mo = rm[tid];
            float tm = fmaxf(fmaxf(red[tid], red[128 + tid]),
                             fmaxf(red[256 + tid], red[384 + tid]));
            const float mn = fmaxf(mo, tm);
            const float al = fast_exp2(mo - mn);
            const float ts = sb[tid] + sb[128 + tid] + sb[256 + tid] + sb[384 + tid];
            rl[tid] = rl[tid] * al + ts;
            rm[tid] = mn;
            ab[tid] = al;
        }
        __syncthreads();

        // ---- PV: acc_o = acc_o*alpha + P @ V (warp owns 16 rows) ----
        {
            const int r0 = warp * 16 + fr;
            const float al0 = ab[r0], al1 = ab[r0 + 8];
            #pragma unroll
            for (int nt = 0; nt < 8; nt++) {
                acc_o[nt][0] *= al0; acc_o[nt][1] *= al0;
                acc_o[nt][2] *= al1; acc_o[nt][3] *= al1;
            }
            #pragma unroll
            for (int ks = 0; ks < 16; ks++) {
                const int kb = ks * 8 + fc;
                float a[4];
                const float* pp = &Ps[r0 * 132 + kb];
                a[0] = pp[0];
                a[1] = pp[8 * 132];
                a[2] = pp[4];
                a[3] = pp[8 * 132 + 4];
                #pragma unroll
                for (int nt = 0; nt < 8; nt++) {
                    const float* pv = &Vs[kb * 68 + nt * 8 + fr];
                    float bf[2];
                    bf[0] = pv[0];
                    bf[1] = pv[4 * 68];
                    mma8(acc_o[nt], a, bf);
                }
            }
        }
    }

    // ---- normalize and write ----
    {
        const int r0 = warp * 16 + fr;
        const float i0 = 1.0f / rl[r0];
        const float i1 = 1.0f / rl[r0 + 8];
        #pragma unroll
        for (int nt = 0; nt < 8; nt++) {
            const int c = nt * 8 + 2 * fc;
            *(float2*)&Aout[(tb + q0 + r0) * HIDN + h * 64 + c] =
                make_float2(acc_o[nt][0] * i0, acc_o[nt][1] * i0);
            *(float2*)&Aout[(tb + q0 + r0 + 8) * HIDN + h * 64 + c] =
                make_float2(acc_o[nt][2] * i1, acc_o[nt][3] * i1);
        }
    }
}

// ---------------------------------------------------------------------------
// launch
// ---------------------------------------------------------------------------
extern "C" void kernel_launch(void* const* d_in, const int* in_sizes, int n_in,
                              void* d_out, int out_size)
{
    (void)in_sizes; (void)n_in; (void)out_size;
    const float* x    = (const float*)d_in[0];
    const float* mask = (const float*)d_in[1];
    const float* Wq   = (const float*)d_in[2];
    const float* bq   = (const float*)d_in[3];
    const float* Wk   = (const float*)d_in[4];
    const float* bk   = (const float*)d_in[5];
    const float* Wv   = (const float*)d_in[6];
    const float* bv   = (const float*)d_in[7];
    const float* Wo   = (const float*)d_in[8];
    const float* bo   = (const float*)d_in[9];
    float* out = (float*)d_out;

    float *Qp, *Kp, *Vp, *Ap;
    cudaGetSymbolAddress((void**)&Qp, g_Q);
    cudaGetSymbolAddress((void**)&Kp, g_K);
    cudaGetSymbolAddress((void**)&Vp, g_V);
    cudaGetSymbolAddress((void**)&Ap, g_A);

    cudaFuncSetAttribute(fa_kernel, cudaFuncAttributeMaxDynamicSharedMemorySize, FA_SMEM);

    // fused Q/K/V projections (384 tiles in one launch)
    qkv_gemm_kernel<<<dim3(24, 16), 256>>>(x, Wq, bq, Qp, Wk, bk, Kp, Wv, bv, Vp,
                                           TKN, HIDN);
    // fused attention (no HBM score traffic)
    fa_kernel<<<dim3(8, 64), 256, FA_SMEM>>>(Qp, Kp, Vp, mask, Ap);
    // output projection + bias + residual
    gemm_tf32_kernel<<<dim3(16, 16), 256>>>(Ap, Wo, bo, out, x, TKN, HIDN, HIDN);
}

// round 4
// speedup vs baseline: 5.4364x; 1.4038x over previous
#include <cuda_runtime.h>
#include <math.h>
#include <stdint.h>

// Problem constants
#define BATCH 2
#define SEQ   1024
#define TKN   2048      // BATCH*SEQ
#define HIDN  2048
#define NHEADS 32
#define KVN   512       // G*HD = 8*64
#define HD    64

// Scratch (static device arrays: no allocation allowed)
__device__ float g_Q[TKN * HIDN];
__device__ float g_K[TKN * KVN];
__device__ float g_V[TKN * KVN];
__device__ float g_A[TKN * HIDN];

// ---------------------------------------------------------------------------
// helpers
// ---------------------------------------------------------------------------
// pack two fp32 -> bf16x2 (lo = first arg)
__device__ __forceinline__ uint32_t bf2(float lo, float hi) {
    uint32_t r;
    asm("cvt.rn.bf16x2.f32 %0, %1, %2;" : "=r"(r) : "f"(hi), "f"(lo));
    return r;
}

// mma.sync m16n8k16 bf16: D = A*B + D (fp32 accum)
__device__ __forceinline__ void mma16(float d[4], const uint32_t a[4], const uint32_t b[2]) {
    asm volatile(
        "mma.sync.aligned.m16n8k16.row.col.f32.bf16.bf16.f32 "
        "{%0,%1,%2,%3}, {%4,%5,%6,%7}, {%8,%9}, {%0,%1,%2,%3};\n"
        : "+f"(d[0]), "+f"(d[1]), "+f"(d[2]), "+f"(d[3])
        : "r"(a[0]), "r"(a[1]), "r"(a[2]), "r"(a[3]), "r"(b[0]), "r"(b[1]));
}

// fast exp2 via FFMA polynomial (avoids MUFU throughput floor)
__device__ __forceinline__ float fast_exp2(float x) {
    x = fmaxf(x, -125.0f);
    int n = __float2int_rn(x);
    float f = x - (float)n;
    float p = 1.5403530393381609e-4f;
    p = fmaf(p, f, 1.3333558146428443e-3f);
    p = fmaf(p, f, 9.6181291076284772e-3f);
    p = fmaf(p, f, 5.5504108664821580e-2f);
    p = fmaf(p, f, 2.4022650695910071e-1f);
    p = fmaf(p, f, 6.9314718055994531e-1f);
    p = fmaf(p, f, 1.0f);
    return __int_as_float((n + 127) << 23) * p;
}

// ---------------------------------------------------------------------------
// bf16 GEMM core (128x128x16 double-buffered, 8 warps 2x4, warp 64x32).
// As: u32 pairs along k, stride 12 u32 (==4 mod 32 -> conflict-free frags)
// Bs: bf16 [k][n], stride 136 -> u16 gathers are word-broadcast friendly.
// ---------------------------------------------------------------------------
#define PA_STR 12
#define PB_STR 136

// Fused Q/K/V projection: blockIdx.x [0,16)->Q, [16,20)->K, [20,24)->V.
__global__ __launch_bounds__(256) void qkv_gemm_kernel(
    const float* __restrict__ A,
    const float* __restrict__ Wq, const float* __restrict__ bq, float* __restrict__ Cq,
    const float* __restrict__ Wk, const float* __restrict__ bk, float* __restrict__ Ck,
    const float* __restrict__ Wv, const float* __restrict__ bv, float* __restrict__ Cv,
    int M, int K)
{
    const float* B; const float* bias; float* C; int N, nb;
    const int bx = blockIdx.x;
    if (bx < 16)      { B = Wq; bias = bq; C = Cq; N = HIDN; nb = bx * 128; }
    else if (bx < 20) { B = Wk; bias = bk; C = Ck; N = KVN;  nb = (bx - 16) * 128; }
    else              { B = Wv; bias = bv; C = Cv; N = KVN;  nb = (bx - 20) * 128; }

    __shared__ uint32_t       As[2][128 * PA_STR];
    __shared__ unsigned short Bs[2][16 * PB_STR];

    const int tid = threadIdx.x, lane = tid & 31, warp = tid >> 5;
    const int wm = warp >> 2, wn = warp & 3;
    const int mb = blockIdx.y * 128;

    const int am = tid >> 2, ak = (tid & 3) * 4;
    const int bk_ = tid >> 5, bn = lane * 4;

    const float* Aptr = A + (size_t)(mb + am) * K + ak;
    const float* Bptr = B + (size_t)bk_ * N + nb + bn;

    float acc[4][4][4];
    #pragma unroll
    for (int i = 0; i < 4; i++)
        #pragma unroll
        for (int j = 0; j < 4; j++)
            #pragma unroll
            for (int q = 0; q < 4; q++) acc[i][j][q] = 0.0f;

    float4 ra0 = *(const float4*)(Aptr);
    float4 ra1 = *(const float4*)(Aptr + (size_t)64 * K);
    float4 rb0 = *(const float4*)(Bptr);
    float4 rb1 = *(const float4*)(Bptr + (size_t)8 * N);
    As[0][am * PA_STR + (ak >> 1)]            = bf2(ra0.x, ra0.y);
    As[0][am * PA_STR + (ak >> 1) + 1]        = bf2(ra0.z, ra0.w);
    As[0][(am + 64) * PA_STR + (ak >> 1)]     = bf2(ra1.x, ra1.y);
    As[0][(am + 64) * PA_STR + (ak >> 1) + 1] = bf2(ra1.z, ra1.w);
    *(uint32_t*)&Bs[0][bk_ * PB_STR + bn]           = bf2(rb0.x, rb0.y);
    *(uint32_t*)&Bs[0][bk_ * PB_STR + bn + 2]       = bf2(rb0.z, rb0.w);
    *(uint32_t*)&Bs[0][(bk_ + 8) * PB_STR + bn]     = bf2(rb1.x, rb1.y);
    *(uint32_t*)&Bs[0][(bk_ + 8) * PB_STR + bn + 2] = bf2(rb1.z, rb1.w);
    __syncthreads();

    const int fr = lane >> 2, fc = lane & 3;

    const int nCh = K >> 4;
    for (int it = 0; it < nCh; it++) {
        const int cur = it & 1;
        if (it + 1 < nCh) {
            const float* ap = Aptr + (it + 1) * 16;
            const float* bp = Bptr + (size_t)(it + 1) * 16 * N;
            ra0 = *(const float4*)(ap);
            ra1 = *(const float4*)(ap + (size_t)64 * K);
            rb0 = *(const float4*)(bp);
            rb1 = *(const float4*)(bp + (size_t)8 * N);
        }
        uint32_t a[4][4], bfr[4][2];
        #pragma unroll
        for (int mt = 0; mt < 4; mt++) {
            const int row = (wm * 64 + mt * 16 + fr) * PA_STR;
            a[mt][0] = As[cur][row + fc];
            a[mt][1] = As[cur][row + 8 * PA_STR + fc];
            a[mt][2] = As[cur][row + fc + 4];
            a[mt][3] = As[cur][row + 8 * PA_STR + fc + 4];
        }
        #pragma unroll
        for (int nt = 0; nt < 4; nt++) {
            const unsigned short* bp = &Bs[cur][wn * 32 + nt * 8 + fr];
            bfr[nt][0] = (uint32_t)bp[(2 * fc) * PB_STR] |
                         ((uint32_t)bp[(2 * fc + 1) * PB_STR] << 16);
            bfr[nt][1] = (uint32_t)bp[(2 * fc + 8) * PB_STR] |
                         ((uint32_t)bp[(2 * fc + 9) * PB_STR] << 16);
        }
        #pragma unroll
        for (int mt = 0; mt < 4; mt++)
            #pragma unroll
            for (int nt = 0; nt < 4; nt++)
                mma16(acc[mt][nt], a[mt], bfr[nt]);

        if (it + 1 < nCh) {
            const int nx = (it + 1) & 1;
            As[nx][am * PA_STR + (ak >> 1)]            = bf2(ra0.x, ra0.y);
            As[nx][am * PA_STR + (ak >> 1) + 1]        = bf2(ra0.z, ra0.w);
            As[nx][(am + 64) * PA_STR + (ak >> 1)]     = bf2(ra1.x, ra1.y);
            As[nx][(am + 64) * PA_STR + (ak >> 1) + 1] = bf2(ra1.z, ra1.w);
            *(uint32_t*)&Bs[nx][bk_ * PB_STR + bn]           = bf2(rb0.x, rb0.y);
            *(uint32_t*)&Bs[nx][bk_ * PB_STR + bn + 2]       = bf2(rb0.z, rb0.w);
            *(uint32_t*)&Bs[nx][(bk_ + 8) * PB_STR + bn]     = bf2(rb1.x, rb1.y);
            *(uint32_t*)&Bs[nx][(bk_ + 8) * PB_STR + bn + 2] = bf2(rb1.z, rb1.w);
        }
        __syncthreads();
    }

    const int r0 = mb + wm * 64 + fr;
    const int c0 = nb + wn * 32 + fc * 2;
    #pragma unroll
    for (int mt = 0; mt < 4; mt++) {
        #pragma unroll
        for (int nt = 0; nt < 4; nt++) {
            const int r = r0 + mt * 16;
            const int c = c0 + nt * 8;
            const float bx_ = bias[c], by = bias[c + 1];
            *(float2*)&C[(size_t)r * N + c] =
                make_float2(acc[mt][nt][0] + bx_, acc[mt][nt][1] + by);
            *(float2*)&C[(size_t)(r + 8) * N + c] =
                make_float2(acc[mt][nt][2] + bx_, acc[mt][nt][3] + by);
        }
    }
}

// O projection with bias + residual (same core).
__global__ __launch_bounds__(256) void gemm_bf16_kernel(
    const float* __restrict__ A,
    const float* __restrict__ B,  const float* __restrict__ bias,  float* __restrict__ C,
    const float* __restrict__ resid,
    int M, int N, int K)
{
    __shared__ uint32_t       As[2][128 * PA_STR];
    __shared__ unsigned short Bs[2][16 * PB_STR];

    const int tid = threadIdx.x, lane = tid & 31, warp = tid >> 5;
    const int wm = warp >> 2, wn = warp & 3;
    const int mb = blockIdx.y * 128, nb = blockIdx.x * 128;

    const int am = tid >> 2, ak = (tid & 3) * 4;
    const int bk_ = tid >> 5, bn = lane * 4;

    const float* Aptr = A + (size_t)(mb + am) * K + ak;
    const float* Bptr = B + (size_t)bk_ * N + nb + bn;

    float acc[4][4][4];
    #pragma unroll
    for (int i = 0; i < 4; i++)
        #pragma unroll
        for (int j = 0; j < 4; j++)
            #pragma unroll
            for (int q = 0; q < 4; q++) acc[i][j][q] = 0.0f;

    float4 ra0 = *(const float4*)(Aptr);
    float4 ra1 = *(const float4*)(Aptr + (size_t)64 * K);
    float4 rb0 = *(const float4*)(Bptr);
    float4 rb1 = *(const float4*)(Bptr + (size_t)8 * N);
    As[0][am * PA_STR + (ak >> 1)]            = bf2(ra0.x, ra0.y);
    As[0][am * PA_STR + (ak >> 1) + 1]        = bf2(ra0.z, ra0.w);
    As[0][(am + 64) * PA_STR + (ak >> 1)]     = bf2(ra1.x, ra1.y);
    As[0][(am + 64) * PA_STR + (ak >> 1) + 1] = bf2(ra1.z, ra1.w);
    *(uint32_t*)&Bs[0][bk_ * PB_STR + bn]           = bf2(rb0.x, rb0.y);
    *(uint32_t*)&Bs[0][bk_ * PB_STR + bn + 2]       = bf2(rb0.z, rb0.w);
    *(uint32_t*)&Bs[0][(bk_ + 8) * PB_STR + bn]     = bf2(rb1.x, rb1.y);
    *(uint32_t*)&Bs[0][(bk_ + 8) * PB_STR + bn + 2] = bf2(rb1.z, rb1.w);
    __syncthreads();

    const int fr = lane >> 2, fc = lane & 3;

    const int nCh = K >> 4;
    for (int it = 0; it < nCh; it++) {
        const int cur = it & 1;
        if (it + 1 < nCh) {
            const float* ap = Aptr + (it + 1) * 16;
            const float* bp = Bptr + (size_t)(it + 1) * 16 * N;
            ra0 = *(const float4*)(ap);
            ra1 = *(const float4*)(ap + (size_t)64 * K);
            rb0 = *(const float4*)(bp);
            rb1 = *(const float4*)(bp + (size_t)8 * N);
        }
        uint32_t a[4][4], bfr[4][2];
        #pragma unroll
        for (int mt = 0; mt < 4; mt++) {
            const int row = (wm * 64 + mt * 16 + fr) * PA_STR;
            a[mt][0] = As[cur][row + fc];
            a[mt][1] = As[cur][row + 8 * PA_STR + fc];
            a[mt][2] = As[cur][row + fc + 4];
            a[mt][3] = As[cur][row + 8 * PA_STR + fc + 4];
        }
        #pragma unroll
        for (int nt = 0; nt < 4; nt++) {
            const unsigned short* bp = &Bs[cur][wn * 32 + nt * 8 + fr];
            bfr[nt][0] = (uint32_t)bp[(2 * fc) * PB_STR] |
                         ((uint32_t)bp[(2 * fc + 1) * PB_STR] << 16);
            bfr[nt][1] = (uint32_t)bp[(2 * fc + 8) * PB_STR] |
                         ((uint32_t)bp[(2 * fc + 9) * PB_STR] << 16);
        }
        #pragma unroll
        for (int mt = 0; mt < 4; mt++)
            #pragma unroll
            for (int nt = 0; nt < 4; nt++)
                mma16(acc[mt][nt], a[mt], bfr[nt]);

        if (it + 1 < nCh) {
            const int nx = (it + 1) & 1;
            As[nx][am * PA_STR + (ak >> 1)]            = bf2(ra0.x, ra0.y);
            As[nx][am * PA_STR + (ak >> 1) + 1]        = bf2(ra0.z, ra0.w);
            As[nx][(am + 64) * PA_STR + (ak >> 1)]     = bf2(ra1.x, ra1.y);
            As[nx][(am + 64) * PA_STR + (ak >> 1) + 1] = bf2(ra1.z, ra1.w);
            *(uint32_t*)&Bs[nx][bk_ * PB_STR + bn]           = bf2(rb0.x, rb0.y);
            *(uint32_t*)&Bs[nx][bk_ * PB_STR + bn + 2]       = bf2(rb0.z, rb0.w);
            *(uint32_t*)&Bs[nx][(bk_ + 8) * PB_STR + bn]     = bf2(rb1.x, rb1.y);
            *(uint32_t*)&Bs[nx][(bk_ + 8) * PB_STR + bn + 2] = bf2(rb1.z, rb1.w);
        }
        __syncthreads();
    }

    const int r0 = mb + wm * 64 + fr;
    const int c0 = nb + wn * 32 + fc * 2;
    #pragma unroll
    for (int mt = 0; mt < 4; mt++) {
        #pragma unroll
        for (int nt = 0; nt < 4; nt++) {
            const int r = r0 + mt * 16;
            const int c = c0 + nt * 8;
            const float bx = bias[c], by = bias[c + 1];
            const float2 u0 = *(const float2*)&resid[(size_t)r * N + c];
            const float2 u1 = *(const float2*)&resid[(size_t)(r + 8) * N + c];
            *(float2*)&C[(size_t)r * N + c] =
                make_float2(acc[mt][nt][0] + bx + u0.x, acc[mt][nt][1] + by + u0.y);
            *(float2*)&C[(size_t)(r + 8) * N + c] =
                make_float2(acc[mt][nt][2] + bx + u1.x, acc[mt][nt][3] + by + u1.y);
        }
    }
}

// ---------------------------------------------------------------------------
// Fused flash attention (bf16 mma). block = (b,h,128 q rows), 8 k-tiles.
// Qs/Ks: u32 pairs along d, stride 36; Ps: u32 pairs along keys, stride 68;
// Vs: bf16 [key][d], stride 72. smem = 95.7 KB -> 2 CTAs/SM.
// ---------------------------------------------------------------------------
#define FQ_STR 36
#define FP_STR 68
#define FV_STR 72

#define FA_QS   0
#define FA_KS   (128 * FQ_STR)               // 4608
#define FA_VS   (2 * 128 * FQ_STR)           // 9216
#define FA_PS   (FA_VS + 128 * FV_STR / 2)   // 13824
#define FA_RED  (FA_PS + 128 * FP_STR)       // 22528
#define FA_SUM  (FA_RED + 512)
#define FA_RM   (FA_SUM + 512)
#define FA_RL   (FA_RM + 128)
#define FA_AB   (FA_RL + 128)
#define FA_U32S (FA_AB + 128)                // 23936
#define FA_SMEM (FA_U32S * 4)                // 95744 B

__global__ __launch_bounds__(256, 2) void fa_kernel(
    const float* __restrict__ Q, const float* __restrict__ K,
    const float* __restrict__ V, const float* __restrict__ mask,
    float* __restrict__ Aout)
{
    extern __shared__ uint32_t shu[];
    uint32_t* Qs = shu + FA_QS;
    uint32_t* Ks = shu + FA_KS;
    unsigned short* Vs = (unsigned short*)(shu + FA_VS);
    uint32_t* Ps = shu + FA_PS;
    float* red = (float*)(shu + FA_RED);
    float* sb  = (float*)(shu + FA_SUM);
    float* rm  = (float*)(shu + FA_RM);
    float* rl  = (float*)(shu + FA_RL);
    float* ab  = (float*)(shu + FA_AB);

    const int tid = threadIdx.x, lane = tid & 31, warp = tid >> 5;
    const int z = blockIdx.y, b = z >> 5, h = z & 31, g = h >> 2;
    const int q0 = blockIdx.x * 128;
    const size_t tb = (size_t)b * SEQ;
    const float* mbase = mask + (size_t)b * SEQ * SEQ;

    const int wm = warp >> 2, wn = warp & 3;
    const int fr = lane >> 2, fc = lane & 3;

    // load Q tile, prescale by (1/8)*log2(e), pack bf16
    const float qsc = 0.125f * 1.4426950408889634f;
    {
        const int r = tid >> 4, c = (tid & 15) * 4;
        #pragma unroll
        for (int p = 0; p < 8; p++) {
            const int row = r + p * 16;
            float4 v = *(const float4*)&Q[(tb + q0 + row) * HIDN + h * 64 + c];
            Qs[row * FQ_STR + (c >> 1)]     = bf2(v.x * qsc, v.y * qsc);
            Qs[row * FQ_STR + (c >> 1) + 1] = bf2(v.z * qsc, v.w * qsc);
        }
    }
    if (tid < 128) { rm[tid] = -1e30f; rl[tid] = 0.0f; }

    float acc_o[8][4];
    #pragma unroll
    for (int i = 0; i < 8; i++)
        #pragma unroll
        for (int q = 0; q < 4; q++) acc_o[i][q] = 0.0f;

    for (int t = 0; t < 8; t++) {
        __syncthreads();  // prev PV done with Ks/Vs; first iter: Qs/rm ready
        {
            const int r = tid >> 4, c = (tid & 15) * 4;
            #pragma unroll
            for (int p = 0; p < 8; p++) {
                const int row = r + p * 16;
                const size_t goff = (tb + t * 128 + row) * KVN + g * 64 + c;
                float4 kw = *(const float4*)&K[goff];
                float4 vw = *(const float4*)&V[goff];
                Ks[row * FQ_STR + (c >> 1)]     = bf2(kw.x, kw.y);
                Ks[row * FQ_STR + (c >> 1) + 1] = bf2(kw.z, kw.w);
                *(uint32_t*)&Vs[row * FV_STR + c]     = bf2(vw.x, vw.y);
                *(uint32_t*)&Vs[row * FV_STR + c + 2] = bf2(vw.z, vw.w);
            }
        }
        __syncthreads();

        // ---- S = Qs @ Ks^T (warp 64x32), 4 k16 steps over d=64 ----
        float s[4][4][4];
        #pragma unroll
        for (int i = 0; i < 4; i++)
            #pragma unroll
            for (int j = 0; j < 4; j++)
                #pragma unroll
                for (int q = 0; q < 4; q++) s[i][j][q] = 0.0f;

        #pragma unroll
        for (int ks = 0; ks < 4; ks++) {
            const int kb = ks * 8 + fc;
            uint32_t a[4][4], bfr[4][2];
            #pragma unroll
            for (int mt = 0; mt < 4; mt++) {
                const int row = (wm * 64 + mt * 16 + fr) * FQ_STR;
                a[mt][0] = Qs[row + kb];
                a[mt][1] = Qs[row + 8 * FQ_STR + kb];
                a[mt][2] = Qs[row + kb + 4];
                a[mt][3] = Qs[row + 8 * FQ_STR + kb + 4];
            }
            #pragma unroll
            for (int nt = 0; nt < 4; nt++) {
                const int row = (wn * 32 + nt * 8 + fr) * FQ_STR;
                bfr[nt][0] = Ks[row + kb];
                bfr[nt][1] = Ks[row + kb + 4];
            }
            #pragma unroll
            for (int mt = 0; mt < 4; mt++)
                #pragma unroll
                for (int nt = 0; nt < 4; nt++)
                    mma16(s[mt][nt], a[mt], bfr[nt]);
        }

        // ---- mask multiply + per-row tile max ----
        #pragma unroll
        for (int mt = 0; mt < 4; mt++) {
            const int r0 = wm * 64 + mt * 16 + fr;
            float m0 = -1e30f, m1 = -1e30f;
            #pragma unroll
            for (int nt = 0; nt < 4; nt++) {
                const int cg = t * 128 + wn * 32 + nt * 8 + 2 * fc;
                const float2 k0 = *(const float2*)&mbase[(size_t)(q0 + r0) * SEQ + cg];
                const float2 k1 = *(const float2*)&mbase[(size_t)(q0 + r0 + 8) * SEQ + cg];
                s[mt][nt][0] *= k0.x; s[mt][nt][1] *= k0.y;
                s[mt][nt][2] *= k1.x; s[mt][nt][3] *= k1.y;
                m0 = fmaxf(m0, fmaxf(s[mt][nt][0], s[mt][nt][1]));
                m1 = fmaxf(m1, fmaxf(s[mt][nt][2], s[mt][nt][3]));
            }
            m0 = fmaxf(m0, __shfl_xor_sync(0xffffffffu, m0, 1));
            m0 = fmaxf(m0, __shfl_xor_sync(0xffffffffu, m0, 2));
            m1 = fmaxf(m1, __shfl_xor_sync(0xffffffffu, m1, 1));
            m1 = fmaxf(m1, __shfl_xor_sync(0xffffffffu, m1, 2));
            if (fc == 0) {
                red[wn * 128 + r0]     = m0;
                red[wn * 128 + r0 + 8] = m1;
            }
        }
        __syncthreads();

        // ---- p = exp2(s - m_new), stage P (bf16 pairs), partial sums ----
        #pragma unroll
        for (int mt = 0; mt < 4; mt++) {
            const int r0 = wm * 64 + mt * 16 + fr;
            const int r1 = r0 + 8;
            float mn0 = fmaxf(fmaxf(red[r0], red[128 + r0]),
                              fmaxf(red[256 + r0], red[384 + r0]));
            float mn1 = fmaxf(fmaxf(red[r1], red[128 + r1]),
                              fmaxf(red[256 + r1], red[384 + r1]));
            mn0 = fmaxf(mn0, rm[r0]);
            mn1 = fmaxf(mn1, rm[r1]);
            float s0 = 0.0f, s1 = 0.0f;
            #pragma unroll
            for (int nt = 0; nt < 4; nt++) {
                const float p0 = fast_exp2(s[mt][nt][0] - mn0);
                const float p1 = fast_exp2(s[mt][nt][1] - mn0);
                const float p2 = fast_exp2(s[mt][nt][2] - mn1);
                const float p3 = fast_exp2(s[mt][nt][3] - mn1);
                s0 += p0 + p1; s1 += p2 + p3;
                const int cw = wn * 16 + nt * 4 + fc;
                Ps[r0 * FP_STR + cw] = bf2(p0, p1);
                Ps[r1 * FP_STR + cw] = bf2(p2, p3);
            }
            s0 += __shfl_xor_sync(0xffffffffu, s0, 1);
            s0 += __shfl_xor_sync(0xffffffffu, s0, 2);
            s1 += __shfl_xor_sync(0xffffffffu, s1, 1);
            s1 += __shfl_xor_sync(0xffffffffu, s1, 2);
            if (fc == 0) {
                sb[wn * 128 + r0] = s0;
                sb[wn * 128 + r1] = s1;
            }
        }
        __syncthreads();

        // ---- per-row running state update ----
        if (tid < 128) {
            const float mo = rm[tid];
            float tm = fmaxf(fmaxf(red[tid], red[128 + tid]),
                             fmaxf(red[256 + tid], red[384 + tid]));
            const float mn = fmaxf(mo, tm);
            const float al = fast_exp2(mo - mn);
            const float ts = sb[tid] + sb[128 + tid] + sb[256 + tid] + sb[384 + tid];
            rl[tid] = rl[tid] * al + ts;
            rm[tid] = mn;
            ab[tid] = al;
        }
        __syncthreads();

        // ---- PV: acc_o = acc_o*alpha + P @ V, 8 k16 steps over 128 keys ----
        {
            const int r0 = warp * 16 + fr;
            const float al0 = ab[r0], al1 = ab[r0 + 8];
            #pragma unroll
            for (int nt = 0; nt < 8; nt++) {
                acc_o[nt][0] *= al0; acc_o[nt][1] *= al0;
                acc_o[nt][2] *= al1; acc_o[nt][3] *= al1;
            }
            #pragma unroll
            for (int ks = 0; ks < 8; ks++) {
                uint32_t a[4];
                const int base = r0 * FP_STR + ks * 8 + fc;
                a[0] = Ps[base];
                a[1] = Ps[base + 8 * FP_STR];
                a[2] = Ps[base + 4];
                a[3] = Ps[base + 8 * FP_STR + 4];
                const int k0r = ks * 16 + 2 * fc;
                #pragma unroll
                for (int nt = 0; nt < 8; nt++) {
                    const unsigned short* vp = &Vs[nt * 8 + fr];
                    uint32_t bfr[2];
                    bfr[0] = (uint32_t)vp[k0r * FV_STR] |
                             ((uint32_t)vp[(k0r + 1) * FV_STR] << 16);
                    bfr[1] = (uint32_t)vp[(k0r + 8) * FV_STR] |
                             ((uint32_t)vp[(k0r + 9) * FV_STR] << 16);
                    mma16(acc_o[nt], a, bfr);
                }
            }
        }
    }

    // ---- normalize and write ----
    {
        const int r0 = warp * 16 + fr;
        const float i0 = 1.0f / rl[r0];
        const float i1 = 1.0f / rl[r0 + 8];
        #pragma unroll
        for (int nt = 0; nt < 8; nt++) {
            const int c = nt * 8 + 2 * fc;
            *(float2*)&Aout[(tb + q0 + r0) * HIDN + h * 64 + c] =
                make_float2(acc_o[nt][0] * i0, acc_o[nt][1] * i0);
            *(float2*)&Aout[(tb + q0 + r0 + 8) * HIDN + h * 64 + c] =
                make_float2(acc_o[nt][2] * i1, acc_o[nt][3] * i1);
        }
    }
}

// ---------------------------------------------------------------------------
// launch
// ---------------------------------------------------------------------------
extern "C" void kernel_launch(void* const* d_in, const int* in_sizes, int n_in,
                              void* d_out, int out_size)
{
    (void)in_sizes; (void)n_in; (void)out_size;
    const float* x    = (const float*)d_in[0];
    const float* mask = (const float*)d_in[1];
    const float* Wq   = (const float*)d_in[2];
    const float* bq   = (const float*)d_in[3];
    const float* Wk   = (const float*)d_in[4];
    const float* bk   = (const float*)d_in[5];
    const float* Wv   = (const float*)d_in[6];
    const float* bv   = (const float*)d_in[7];
    const float* Wo   = (const float*)d_in[8];
    const float* bo   = (const float*)d_in[9];
    float* out = (float*)d_out;

    float *Qp, *Kp, *Vp, *Ap;
    cudaGetSymbolAddress((void**)&Qp, g_Q);
    cudaGetSymbolAddress((void**)&Kp, g_K);
    cudaGetSymbolAddress((void**)&Vp, g_V);
    cudaGetSymbolAddress((void**)&Ap, g_A);

    cudaFuncSetAttribute(fa_kernel, cudaFuncAttributeMaxDynamicSharedMemorySize, FA_SMEM);

    // fused Q/K/V projections
    qkv_gemm_kernel<<<dim3(24, 16), 256>>>(x, Wq, bq, Qp, Wk, bk, Kp, Wv, bv, Vp,
                                           TKN, HIDN);
    // fused attention
    fa_kernel<<<dim3(8, 64), 256, FA_SMEM>>>(Qp, Kp, Vp, mask, Ap);
    // output projection + bias + residual
    gemm_bf16_kernel<<<dim3(16, 16), 256>>>(Ap, Wo, bo, out, x, TKN, HIDN, HIDN);
}